// round 11
// baseline (speedup 1.0000x reference)
#include <cuda_runtime.h>
#include <cstdint>

#define NN 50000
#define EE 800000
#define BDIM 64          // NBASES*FH
#define CWDIM 32         // NHEADS*NBASES

// ------------- scratch (device globals; referenced ONLY in device code) -----
__device__ float g_dis[NN];
__device__ int   g_row[EE];
__device__ int   g_col[EE];
__device__ __align__(16) float g_sb [NN * BDIM];   // dis-scaled bases
__device__ __align__(16) float g_agg[NN * BDIM];
__device__ float g_cw [NN * CWDIM];  // combination weights per node
__device__ float g_h1 [NN * 128];
__device__ float g_h2 [NN * 128];
__device__ float g_pre0[NN * 2];
__device__ float g_pre1[NN * 2];
__device__ int   g_is64;

// ------------- dtype detection (int64 vs int32 edge_index) -----------------
__global__ void k_detect(const unsigned int* __restrict__ ei_words) {
    __shared__ int nz;
    int t = threadIdx.x;  // 128 threads
    if (t == 0) nz = 0;
    __syncthreads();
    unsigned int w = ei_words[2 * (t * 997 + 1) + 1];
    if (w != 0) atomicOr(&nz, 1);
    __syncthreads();
    if (t == 0) g_is64 = (nz == 0);
}

// ------------- degree / symnorm --------------------------------------------
__global__ void k_init_dis() {
    int v = blockIdx.x * blockDim.x + threadIdx.x;
    if (v < NN) g_dis[v] = 1.0f;   // self-loop contribution
}

__global__ void k_prep_edges(const void* __restrict__ ei) {
    int e = blockIdx.x * blockDim.x + threadIdx.x;
    if (e >= EE) return;
    int r, c;
    if (g_is64) {
        const long long* p = (const long long*)ei;
        r = (int)p[e];
        c = (int)p[EE + e];
    } else {
        const int* p = (const int*)ei;
        r = p[e];
        c = p[EE + e];
    }
    g_row[e] = r;
    g_col[e] = c;
    atomicAdd(&g_dis[c], 1.0f);
}

__global__ void k_rsqrt_dis() {
    int v = blockIdx.x * blockDim.x + threadIdx.x;
    if (v < NN) g_dis[v] = rsqrtf(g_dis[v]);
}

// ------------- fused GEMM: [N,128] x [128, 64+32] ---------------------------
// layer==0: X = x (param). layer==1: X = g_h1 (device global, in device code!)
// writes g_sb (cols 0..63, scaled by dis) and g_cw (cols 64..95, + bc)
__global__ void k_gemm(const float* __restrict__ Xin, int layer,
                       const float* __restrict__ Wb,
                       const float* __restrict__ Wc,
                       const float* __restrict__ bc) {
    const float* X = (layer == 0) ? Xin : g_h1;
    __shared__ float Xs[32][33];   // 32 rows x 32 K
    __shared__ float Ws[32][96];   // 32 K x 96 cols
    int row0 = blockIdx.x * 32;
    int tx = threadIdx.x;          // 256
    int r  = tx >> 3;              // 0..31 (row within tile)
    int cg = tx & 7;               // 0..7  (12 cols each)

    float acc[12];
#pragma unroll
    for (int j = 0; j < 12; j++) acc[j] = 0.f;

    for (int kb = 0; kb < 4; kb++) {
        for (int i = tx; i < 32 * 32; i += 256) {
            int rr = i >> 5, kk = i & 31;
            int grow = row0 + rr;
            Xs[rr][kk] = (grow < NN) ? X[grow * 128 + kb * 32 + kk] : 0.f;
        }
        for (int i = tx; i < 32 * 96; i += 256) {
            int kk = i / 96, cc = i % 96;
            int k = kb * 32 + kk;
            Ws[kk][cc] = (cc < 64) ? Wb[k * 64 + cc] : Wc[k * 32 + (cc - 64)];
        }
        __syncthreads();
#pragma unroll
        for (int k = 0; k < 32; k++) {
            float xv = Xs[r][k];
#pragma unroll
            for (int j = 0; j < 12; j++)
                acc[j] += xv * Ws[k][cg * 12 + j];
        }
        __syncthreads();
    }

    int grow = row0 + r;
    if (grow < NN) {
        float dv = g_dis[grow];
#pragma unroll
        for (int j = 0; j < 12; j++) {
            int c = cg * 12 + j;
            if (c < 64) g_sb[grow * 64 + c] = dv * acc[j];
            else        g_cw[grow * 32 + (c - 64)] = acc[j] + bc[c - 64];
        }
    }
}

// ------------- zero agg -----------------------------------------------------
__global__ void k_zero_agg() {
    int t = blockIdx.x * blockDim.x + threadIdx.x;
    if (t < NN * BDIM) g_agg[t] = 0.f;
}

// ------------- scatter-add: agg[col] += sb[row] (v4 reductions) -------------
__global__ void k_scatter() {
    int t = blockIdx.x * blockDim.x + threadIdx.x;   // E*16 = 12.8M
    if (t >= EE * 16) return;
    int e = t >> 4;
    int q = t & 15;
    int r = g_row[e];
    int c = g_col[e];
    const float4 v = *(const float4*)(g_sb + r * 64 + q * 4);
    float* p = g_agg + c * 64 + q * 4;
    asm volatile("red.global.add.v4.f32 [%0], {%1,%2,%3,%4};"
                 :: "l"(p), "f"(v.x), "f"(v.y), "f"(v.z), "f"(v.w)
                 : "memory");
}

// ------------- per-node combine + bias (+optional relu) ---------------------
// h[v][hh*16+f] = sum_b cw[hh*4+b] * (dis[v]*(agg+sb))[b*16+f] + bias
// layer==0 -> write g_h1 with relu; layer==1 -> write g_h2 no relu
__global__ void k_combine(const float* __restrict__ bias, int layer) {
    int t = blockIdx.x * blockDim.x + threadIdx.x;
    if (t >= NN * 128) return;
    int v  = t >> 7;
    int j  = t & 127;
    int hh = j >> 4;
    int f  = j & 15;
    float dv = g_dis[v];
    float s = 0.f;
#pragma unroll
    for (int b = 0; b < 4; b++) {
        float a = dv * (g_agg[v * 64 + b * 16 + f] + g_sb[v * 64 + b * 16 + f]);
        s += g_cw[v * 32 + hh * 4 + b] * a;
    }
    s += bias[j];
    if (layer == 0) g_h1[t] = fmaxf(s, 0.f);
    else            g_h2[t] = s;
}

// ------------- classifier precompute: pre0 = h2@Wcls[:128], pre1 = h2@Wcls[128:]
__global__ void k_precls(const float* __restrict__ Wcls) {
    int gt = blockIdx.x * blockDim.x + threadIdx.x;
    int v = gt >> 5;
    int lane = gt & 31;
    if (v >= NN) return;
    float a00 = 0.f, a01 = 0.f, a10 = 0.f, a11 = 0.f;
#pragma unroll
    for (int i = 0; i < 4; i++) {
        int k = lane + i * 32;
        float hv = g_h2[v * 128 + k];
        a00 += hv * Wcls[k * 2 + 0];
        a01 += hv * Wcls[k * 2 + 1];
        a10 += hv * Wcls[(128 + k) * 2 + 0];
        a11 += hv * Wcls[(128 + k) * 2 + 1];
    }
#pragma unroll
    for (int o = 16; o; o >>= 1) {
        a00 += __shfl_xor_sync(0xffffffffu, a00, o);
        a01 += __shfl_xor_sync(0xffffffffu, a01, o);
        a10 += __shfl_xor_sync(0xffffffffu, a10, o);
        a11 += __shfl_xor_sync(0xffffffffu, a11, o);
    }
    if (lane == 0) {
        g_pre0[v * 2 + 0] = a00;
        g_pre0[v * 2 + 1] = a01;
        g_pre1[v * 2 + 0] = a10;
        g_pre1[v * 2 + 1] = a11;
    }
}

// ------------- edge output: out[e][o] = pre0[src][o] + pre1[dst][o] + bcls[o]
__global__ void k_edgeout(const float* __restrict__ bcls,
                          float* __restrict__ out) {
    int t = blockIdx.x * blockDim.x + threadIdx.x;
    if (t >= EE * 2) return;
    int e = t >> 1;
    int o = t & 1;
    out[t] = g_pre0[g_row[e] * 2 + o] + g_pre1[g_col[e] * 2 + o] + bcls[o];
}

// ------------- launch: resolve inputs BY SIZE (order-agnostic) --------------
extern "C" void kernel_launch(void* const* d_in, const int* in_sizes, int n_in,
                              void* d_out, int out_size) {
    const float *x = 0, *Wb1 = 0, *Wc1 = 0, *bc1 = 0, *b1 = 0;
    const float *Wb2 = 0, *Wc2 = 0, *bc2 = 0, *b2 = 0, *Wcls = 0, *bcls = 0;
    const void* ei = 0;

    // Within equal-size pairs, the "1" tensor precedes the "2" tensor both in
    // dict-insertion and lexicographic order, so first-hit-wins is safe.
    for (int i = 0; i < n_in; i++) {
        const float* p = (const float*)d_in[i];
        switch (in_sizes[i]) {
            case 6400000: x = p; break;                       // [50000,128]
            case 1600000: ei = d_in[i]; break;                // [2,800000]
            case 8192:    if (!Wb1) Wb1 = p; else Wb2 = p; break;
            case 4096:    if (!Wc1) Wc1 = p; else Wc2 = p; break;
            case 512:     Wcls = p; break;
            case 128:     if (!b1) b1 = p; else b2 = p; break;
            case 32:      if (!bc1) bc1 = p; else bc2 = p; break;
            case 2:       bcls = p; break;
            default: break;
        }
    }
    // positional fallback (canonical dict order) if size match failed
    if (!x && n_in >= 12) {
        x = (const float*)d_in[0]; ei = d_in[1];
        Wb1 = (const float*)d_in[2]; Wc1 = (const float*)d_in[3];
        bc1 = (const float*)d_in[4]; b1 = (const float*)d_in[5];
        Wb2 = (const float*)d_in[6]; Wc2 = (const float*)d_in[7];
        bc2 = (const float*)d_in[8]; b2 = (const float*)d_in[9];
        Wcls = (const float*)d_in[10]; bcls = (const float*)d_in[11];
    }
    float* out = (float*)d_out;

    k_detect<<<1, 128>>>((const unsigned int*)ei);
    k_init_dis<<<(NN + 255) / 256, 256>>>();
    k_prep_edges<<<(EE + 255) / 256, 256>>>(ei);
    k_rsqrt_dis<<<(NN + 255) / 256, 256>>>();

    // ---- layer 1 ----
    k_gemm<<<(NN + 31) / 32, 256>>>(x, 0, Wb1, Wc1, bc1);
    k_zero_agg<<<(NN * BDIM + 255) / 256, 256>>>();
    k_scatter<<<(EE * 16 + 255) / 256, 256>>>();
    k_combine<<<(NN * 128 + 255) / 256, 256>>>(b1, 0);

    // ---- layer 2 ----
    k_gemm<<<(NN + 31) / 32, 256>>>(x, 1, Wb2, Wc2, bc2);
    k_zero_agg<<<(NN * BDIM + 255) / 256, 256>>>();
    k_scatter<<<(EE * 16 + 255) / 256, 256>>>();
    k_combine<<<(NN * 128 + 255) / 256, 256>>>(b2, 1);

    // ---- edge classifier ----
    k_precls<<<(NN * 32 + 255) / 256, 256>>>(Wcls);
    k_edgeout<<<(EE * 2 + 255) / 256, 256>>>(bcls, out);
}